// round 8
// baseline (speedup 1.0000x reference)
#include <cuda_runtime.h>
#include <cstdint>

// MeanAggregator: out[b, :] = (1/K) * sum_k features[neigh_idx[b,k], :]
// features: [1e6, 128] fp32 (512 MB), neigh_idx: [1e5, 10] int32, out: [1e5,128] fp32.
//
// Winning shape (R2->R7): one-shot grid, one warp per output row, lane l owns
// float4 chunk l (32 x 16B = 512B = one feature row) -> every gathered row is
// one fully coalesced 512B access; K=10 fully unrolled -> 10 independent
// LDG.128 front-batched per warp; regs capped at 32 for 64 warps/SM.
// (2 rows/warp, persistent loop, L2 policy hints: all regressed or neutral.)
//
// R8 change: 128-thread blocks, 16 blocks/SM. Same 64 warps/SM theoretical,
// but half-size resource grains -> block-exit churn and tail-wave waste drop,
// raising ACHIEVED occupancy (was 82.3% of 64). Traffic and per-warp code
// unchanged.

#define D 128
#define KNEIGH 10

__global__ __launch_bounds__(128, 16) void mean_agg_kernel(
    const float* __restrict__ features,
    const int* __restrict__ neigh_idx,
    float* __restrict__ out,
    int B)
{
    const int warp_global = (blockIdx.x * blockDim.x + threadIdx.x) >> 5;
    const int lane = threadIdx.x & 31;
    if (warp_global >= B) return;

    // Lanes 0..9 each load one neighbor index for this row, broadcast via shfl.
    int my_idx = 0;
    if (lane < KNEIGH) {
        my_idx = __ldg(neigh_idx + (long long)warp_global * KNEIGH + lane);
    }

    float4 acc = make_float4(0.f, 0.f, 0.f, 0.f);

    #pragma unroll
    for (int k = 0; k < KNEIGH; ++k) {
        long long j = __shfl_sync(0xffffffffu, my_idx, k);
        float4 v = __ldg(reinterpret_cast<const float4*>(features + j * D) + lane);
        acc.x += v.x;
        acc.y += v.y;
        acc.z += v.z;
        acc.w += v.w;
    }

    const float inv_k = 1.0f / (float)KNEIGH;
    float4 r = make_float4(acc.x * inv_k, acc.y * inv_k, acc.z * inv_k, acc.w * inv_k);
    reinterpret_cast<float4*>(out + (long long)warp_global * D)[lane] = r;
}

extern "C" void kernel_launch(void* const* d_in, const int* in_sizes, int n_in,
                              void* d_out, int out_size)
{
    const float* features = (const float*)d_in[0];
    const int* neigh_idx  = (const int*)d_in[1];
    float* out            = (float*)d_out;

    const int B = in_sizes[1] / KNEIGH;   // 100,000

    const int warps_per_block = 128 / 32; // 4
    const int grid = (B + warps_per_block - 1) / warps_per_block; // 25,000

    mean_agg_kernel<<<grid, 128>>>(features, neigh_idx, out, B);
}

// round 9
// speedup vs baseline: 1.0105x; 1.0105x over previous
#include <cuda_runtime.h>
#include <cstdint>

// MeanAggregator: out[b, :] = (1/K) * sum_k features[neigh_idx[b,k], :]
// features: [1e6, 128] fp32 (512 MB), neigh_idx: [1e5, 10] int32, out: [1e5,128] fp32.
//
// Winning shape (R7, 75.9us): one-shot grid, one warp per output row, lane l
// owns float4 chunk l (32 x 16B = 512B = one feature row) -> every gathered
// row is one fully coalesced 512B access; K=10 fully unrolled -> 10
// independent LDG.128 front-batched; __launch_bounds__(256, 8) -> 32 regs,
// 64 warps/SM. (2 rows/warp, persistent loop, 128-thr blocks, L2 policy
// hints: all regressed or neutral.)
//
// R9 change: cache-path hygiene on the same shape.
//   - gathers: ld.global.cg (L2-only). Random rows have ~0 L1 reuse; skip the
//     L1 allocate/fill work in front of the L1tex wavefront queue.
//   - stores:  st.global.cs (evict-first). 51 MB of touch-once output lines
//     stop displacing feature rows from L2.

#define D 128
#define KNEIGH 10

__device__ __forceinline__ float4 ldg_cg(const float4* p) {
    float4 v;
    asm volatile("ld.global.cg.v4.f32 {%0,%1,%2,%3}, [%4];"
                 : "=f"(v.x), "=f"(v.y), "=f"(v.z), "=f"(v.w)
                 : "l"(p));
    return v;
}

__global__ __launch_bounds__(256, 8) void mean_agg_kernel(
    const float* __restrict__ features,
    const int* __restrict__ neigh_idx,
    float* __restrict__ out,
    int B)
{
    const int warp_global = (blockIdx.x * blockDim.x + threadIdx.x) >> 5;
    const int lane = threadIdx.x & 31;
    if (warp_global >= B) return;

    // Lanes 0..9 each load one neighbor index for this row, broadcast via shfl.
    int my_idx = 0;
    if (lane < KNEIGH) {
        my_idx = __ldg(neigh_idx + (long long)warp_global * KNEIGH + lane);
    }

    float4 acc = make_float4(0.f, 0.f, 0.f, 0.f);

    #pragma unroll
    for (int k = 0; k < KNEIGH; ++k) {
        long long j = __shfl_sync(0xffffffffu, my_idx, k);
        float4 v = ldg_cg(reinterpret_cast<const float4*>(features + j * D) + lane);
        acc.x += v.x;
        acc.y += v.y;
        acc.z += v.z;
        acc.w += v.w;
    }

    const float inv_k = 1.0f / (float)KNEIGH;
    float4 r = make_float4(acc.x * inv_k, acc.y * inv_k, acc.z * inv_k, acc.w * inv_k);
    __stcs(reinterpret_cast<float4*>(out + (long long)warp_global * D) + lane, r);
}

extern "C" void kernel_launch(void* const* d_in, const int* in_sizes, int n_in,
                              void* d_out, int out_size)
{
    const float* features = (const float*)d_in[0];
    const int* neigh_idx  = (const int*)d_in[1];
    float* out            = (float*)d_out;

    const int B = in_sizes[1] / KNEIGH;   // 100,000

    const int warps_per_block = 256 / 32; // 8
    const int grid = (B + warps_per_block - 1) / warps_per_block; // 12,500

    mean_agg_kernel<<<grid, 256>>>(features, neigh_idx, out, B);
}